// round 5
// baseline (speedup 1.0000x reference)
#include <cuda_runtime.h>

#define NN  69
#define BB  32
#define TT  1024
#define FIN 8
#define H1  32
#define H2  16
#define TW  8      // t-positions per block (one per warp)
#define XS  10     // x row stride in smem (bank spread, 8B aligned)
#define PS  18     // p row stride in smem (bank spread, 8B aligned)

// Scratch (no cudaMalloc allowed): normalized adjacency in ELL form + W1^T
__device__ float         g_vals[NN * NN];
__device__ unsigned char g_cols[NN * NN + 4];
__device__ int           g_cnt[NN];
__device__ float         g_W1t[H1 * FIN];

// ---------------------------------------------------------------------------
// Prep: adj_n = D^-1/2 (A + I) D^-1/2, packed per-row sparse; W1 transpose.
// ---------------------------------------------------------------------------
__global__ void prep_kernel(const float* __restrict__ adj,
                            const float* __restrict__ W1) {
    __shared__ float dis[NN];
    int tid = threadIdx.x;
    if (tid < NN) {
        float d = 1.0f;  // +I contributes 1 to every row sum
        for (int m = 0; m < NN; m++) d += adj[tid * NN + m];
        dis[tid] = rsqrtf(d);
    }
    __syncthreads();
    if (tid < NN) {
        float di = dis[tid];
        int cnt = 0;
        for (int m = 0; m < NN; m++) {
            float v = adj[tid * NN + m];
            if (m == tid) v += 1.0f;          // A + I (diag may become 2)
            if (v != 0.0f) {
                g_vals[tid * NN + cnt] = v * di * dis[m];
                g_cols[tid * NN + cnt] = (unsigned char)m;
                cnt++;
            }
        }
        g_cnt[tid] = cnt;
    }
    if (tid < H1 * FIN) {
        int j = tid / FIN, f = tid % FIN;
        g_W1t[tid] = W1[f * H1 + j];          // W1t[j][f] = W1[f][j]
    }
}

// ---------------------------------------------------------------------------
// Fused GCN: per warp, one (b,t):
//   y1 = A_n @ x_t   (sparse, y1 kept in registers per-lane-row)
//   h  = relu(y1 @ W1);  p = h @ W2   (fused, h never materialized)
//   z  = A_n @ p     (sparse);  out = sigmoid(z)
// ---------------------------------------------------------------------------
__global__ __launch_bounds__(256, 2)
void gcn_kernel(const float* __restrict__ x,
                const float* __restrict__ W2,
                float* __restrict__ out) {
    extern __shared__ float sm[];
    float* s_W1t  = sm;                          // 256 floats
    float* s_W2   = s_W1t + H1 * FIN;            // 512 floats
    float* s_x    = s_W2 + H1 * H2;              // TW*NN*XS = 5520
    float* s_p    = s_x + TW * NN * XS;          // TW*NN*PS = 9936
    float* s_vals = s_p + TW * NN * PS;          // 4761
    int*   s_cnt  = (int*)(s_vals + NN * NN);    // 69 ints
    unsigned char* s_cols = (unsigned char*)(s_cnt + NN);  // 4764 bytes

    const int tid = threadIdx.x;
    const int bt0 = blockIdx.x * TW;
    const int b   = bt0 >> 10;          // T = 1024
    const int t0  = bt0 & (TT - 1);

    // ---- cooperative smem fill ----
    for (int i = tid; i < H1 * FIN; i += 256) s_W1t[i] = g_W1t[i];
    for (int i = tid; i < H1 * H2;  i += 256) s_W2[i]  = W2[i];
    for (int i = tid; i < NN * NN;  i += 256) s_vals[i] = g_vals[i];
    for (int i = tid; i < NN;       i += 256) s_cnt[i]  = g_cnt[i];
    {
        const unsigned int* gc = (const unsigned int*)g_cols;
        unsigned int* sc = (unsigned int*)s_cols;
        for (int i = tid; i < (NN * NN + 3) / 4; i += 256) sc[i] = gc[i];
    }
    // x slab: x[n, b, t0..t0+7, 0..7] -> s_x[t][n][f] (stride XS)
    {
        const float2* xg = (const float2*)x;
        for (int i = tid; i < NN * TW * 4; i += 256) {
            int n = i >> 5;        // TW*4 = 32 float2 per n
            int r = i & 31;
            int t = r >> 2;
            int h = r & 3;
            float2 v = xg[((size_t)(n * BB + b) * TT + t0 + t) * 4 + h];
            *(float2*)(s_x + (t * NN + n) * XS + h * 2) = v;
        }
    }
    __syncthreads();

    const int w    = tid >> 5;
    const int lane = tid & 31;
    const int t    = t0 + w;
    float* xw = s_x + w * NN * XS;
    float* pw = s_p + w * NN * PS;

    // ---- stage 1+2: sparse agg1 (regs) -> W1/relu/W2 fold -> p in smem ----
    #pragma unroll 1
    for (int r = 0; r < 3; r++) {
        int n = r * 32 + lane;
        if (n < NN) {
            float y[FIN];
            #pragma unroll
            for (int f = 0; f < FIN; f++) y[f] = 0.0f;

            const int cnt = s_cnt[n];
            const float* vrow = s_vals + n * NN;
            const unsigned char* crow = s_cols + n * NN;
            #pragma unroll 2
            for (int k = 0; k < cnt; k++) {
                float a = vrow[k];
                int m = crow[k];
                const float2* xm = (const float2*)(xw + m * XS);
                float2 q0 = xm[0], q1 = xm[1], q2 = xm[2], q3 = xm[3];
                y[0] += a * q0.x; y[1] += a * q0.y;
                y[2] += a * q1.x; y[3] += a * q1.y;
                y[4] += a * q2.x; y[5] += a * q2.y;
                y[6] += a * q3.x; y[7] += a * q3.y;
            }

            float p[H2];
            #pragma unroll
            for (int k = 0; k < H2; k++) p[k] = 0.0f;

            #pragma unroll 4
            for (int j = 0; j < H1; j++) {
                const float4* w1 = (const float4*)(s_W1t + j * FIN);
                float4 wa = w1[0], wb = w1[1];
                float h = y[0] * wa.x + y[1] * wa.y + y[2] * wa.z + y[3] * wa.w
                        + y[4] * wb.x + y[5] * wb.y + y[6] * wb.z + y[7] * wb.w;
                h = fmaxf(h, 0.0f);
                const float4* w2 = (const float4*)(s_W2 + j * H2);
                float4 c0 = w2[0], c1 = w2[1], c2 = w2[2], c3 = w2[3];
                p[0]  += h * c0.x; p[1]  += h * c0.y; p[2]  += h * c0.z; p[3]  += h * c0.w;
                p[4]  += h * c1.x; p[5]  += h * c1.y; p[6]  += h * c1.z; p[7]  += h * c1.w;
                p[8]  += h * c2.x; p[9]  += h * c2.y; p[10] += h * c2.z; p[11] += h * c2.w;
                p[12] += h * c3.x; p[13] += h * c3.y; p[14] += h * c3.z; p[15] += h * c3.w;
            }

            float2* pr = (float2*)(pw + n * PS);
            #pragma unroll
            for (int k = 0; k < 8; k++) pr[k] = make_float2(p[2 * k], p[2 * k + 1]);
        }
    }
    __syncwarp();

    // ---- stage 3: sparse agg2 + sigmoid + store ----
    #pragma unroll 1
    for (int r = 0; r < 3; r++) {
        int n = r * 32 + lane;
        if (n < NN) {
            float z[H2];
            #pragma unroll
            for (int k = 0; k < H2; k++) z[k] = 0.0f;

            const int cnt = s_cnt[n];
            const float* vrow = s_vals + n * NN;
            const unsigned char* crow = s_cols + n * NN;
            #pragma unroll 2
            for (int k = 0; k < cnt; k++) {
                float a = vrow[k];
                int m = crow[k];
                const float2* pm = (const float2*)(pw + m * PS);
                #pragma unroll
                for (int q = 0; q < 8; q++) {
                    float2 v = pm[q];
                    z[2 * q]     += a * v.x;
                    z[2 * q + 1] += a * v.y;
                }
            }

            float o[H2];
            #pragma unroll
            for (int k = 0; k < H2; k++) o[k] = 1.0f / (1.0f + __expf(-z[k]));

            float4* op = (float4*)(out + (((size_t)b * TT + t) * NN + n) * H2);
            op[0] = make_float4(o[0],  o[1],  o[2],  o[3]);
            op[1] = make_float4(o[4],  o[5],  o[6],  o[7]);
            op[2] = make_float4(o[8],  o[9],  o[10], o[11]);
            op[3] = make_float4(o[12], o[13], o[14], o[15]);
        }
    }
}

// ---------------------------------------------------------------------------
extern "C" void kernel_launch(void* const* d_in, const int* in_sizes, int n_in,
                              void* d_out, int out_size) {
    const float* x   = (const float*)d_in[0];   // [69, 32, 1024, 8]
    const float* adj = (const float*)d_in[1];   // [69, 69]
    const float* W1  = (const float*)d_in[2];   // [8, 32]
    const float* W2  = (const float*)d_in[3];   // [32, 16]
    float* out = (float*)d_out;                 // [32, 1024, 69, 16]

    prep_kernel<<<1, 256>>>(adj, W1);

    const int smem_bytes =
        (H1 * FIN + H1 * H2 + TW * NN * XS + TW * NN * PS + NN * NN) * 4  // floats
        + NN * 4                    // cnt
        + (NN * NN + 3);            // cols (word-padded)
    cudaFuncSetAttribute(gcn_kernel,
                         cudaFuncAttributeMaxDynamicSharedMemorySize, smem_bytes);
    gcn_kernel<<<(BB * TT) / TW, 256, smem_bytes>>>(x, W2, out);
}

// round 9
// speedup vs baseline: 1.0529x; 1.0529x over previous
#include <cuda_runtime.h>

#define NN  69
#define BB  32
#define TT  1024
#define FIN 8
#define H1  32
#define H2  16
#define TW  8      // t-positions per block
#define XS  12     // x row stride (floats) -> 2x LDS.128 per row
#define PS  20     // p row stride (floats) -> 4x LDS.128 per row
#define NTASK (TW * NN)   // 552

typedef unsigned long long u64;

// ---- f32x2 helpers (Blackwell packed fp32) --------------------------------
__device__ __forceinline__ void ffma2(u64& d, u64 a, u64 b) {
    asm("fma.rn.f32x2 %0, %1, %2, %0;" : "+l"(d) : "l"(a), "l"(b));
}
__device__ __forceinline__ u64 dup2(float a) {
    u64 r; asm("mov.b64 %0, {%1, %1};" : "=l"(r) : "f"(a)); return r;
}
__device__ __forceinline__ u64 pack2(float a, float b) {
    u64 r; asm("mov.b64 %0, {%1, %2};" : "=l"(r) : "f"(a), "f"(b)); return r;
}
__device__ __forceinline__ void unpack2(u64 v, float& a, float& b) {
    asm("mov.b64 {%0, %1}, %2;" : "=f"(a), "=f"(b) : "l"(v));
}

// ---- scratch (no cudaMalloc allowed) --------------------------------------
__device__ float         g_vals[NN * NN];
__device__ unsigned char g_cols[NN * NN + 4];
__device__ int           g_cnt[NN];
__device__ float2        g_W2t[H2 * 16];   // [c][j2] = (W2[2j2][c], W2[2j2+1][c])

// ---------------------------------------------------------------------------
// Prep: adj_n = D^-1/2 (A+I) D^-1/2 packed ELL (sorted by m, rotated per row
// for cross-lane bank decorrelation) + W2 pair-transpose.
// ---------------------------------------------------------------------------
__global__ void prep_kernel(const float* __restrict__ adj,
                            const float* __restrict__ W2) {
    __shared__ float dis[NN];
    int tid = threadIdx.x;
    if (tid < NN) {
        float d = 1.0f;
        for (int m = 0; m < NN; m++) d += adj[tid * NN + m];
        dis[tid] = rsqrtf(d);
    }
    __syncthreads();
    if (tid < NN) {
        float di = dis[tid];
        float tv[NN]; int tm[NN];
        int cnt = 0;
        for (int m = 0; m < NN; m++) {          // ascending m
            float v = adj[tid * NN + m];
            if (m == tid) v += 1.0f;
            if (v != 0.0f) { tv[cnt] = v * di * dis[m]; tm[cnt] = m; cnt++; }
        }
        int off = ((tid & 31) * cnt) >> 5;       // lane-phase rotation
        for (int k = 0; k < cnt; k++) {
            int s = k + off; if (s >= cnt) s -= cnt;
            g_vals[tid * NN + k] = tv[s];
            g_cols[tid * NN + k] = (unsigned char)tm[s];
        }
        g_cnt[tid] = cnt;
    }
    if (tid < H2 * 16) {
        int c = tid >> 4, j2 = tid & 15;
        g_W2t[tid] = make_float2(W2[(2 * j2) * H2 + c], W2[(2 * j2 + 1) * H2 + c]);
    }
}

// ---------------------------------------------------------------------------
// Fused GCN, task-flattened (t,n) mapping, f32x2 math.
// ---------------------------------------------------------------------------
__global__ __launch_bounds__(256, 2)
void gcn_kernel(const float* __restrict__ x,
                const float* __restrict__ W1,
                float* __restrict__ out) {
    extern __shared__ float sm[];
    float*  s_W1  = sm;                            // 256 floats  (W1 row-major [8][32])
    float2* s_W2t = (float2*)(sm + 256);           // 256 float2
    float*  s_x   = sm + 256 + 512;                // TW*NN*XS = 6624
    float*  s_p   = s_x + TW * NN * XS;            // TW*NN*PS = 11040
    float*  s_vals = s_p + TW * NN * PS;           // 4761
    int*    s_cnt  = (int*)(s_vals + NN * NN);     // 69
    unsigned char* s_cols = (unsigned char*)(s_cnt + NN);   // 4764 B

    const int tid = threadIdx.x;
    const int bt0 = blockIdx.x * TW;
    const int b   = bt0 >> 10;
    const int t0  = bt0 & (TT - 1);

    // ---- cooperative smem fill ----
    s_W1[tid]  = W1[tid];          // exactly 256 floats
    s_W2t[tid] = g_W2t[tid];       // exactly 256 float2  (BUGFIX: was dead code)
    for (int i = tid; i < NN * NN; i += 256) s_vals[i] = g_vals[i];
    if (tid < NN) s_cnt[tid] = g_cnt[tid];
    {
        const unsigned int* gc = (const unsigned int*)g_cols;
        unsigned int* sc = (unsigned int*)s_cols;
        for (int i = tid; i < (NN * NN + 3) / 4; i += 256) sc[i] = gc[i];
    }
    {   // x slab: [n][b][t0+t][f] -> s_x[t][n][0..7], float4 moves
        const float4* xg = (const float4*)x;
        for (int i = tid; i < NN * TW * 2; i += 256) {
            int n = i >> 4;
            int r = i & 15;
            int t = r >> 1, h = r & 1;
            float4 v = xg[((size_t)(n * BB + b) * TT + t0 + t) * 2 + h];
            *(float4*)(s_x + (t * NN + n) * XS + h * 4) = v;
        }
    }
    __syncthreads();

    // =========== Phase A: per (t,n): sparse agg1 -> FC1 relu FC2 -> p ======
    #pragma unroll 1
    for (int r = 0; r < 3; r++) {
        int i = tid + (r << 8);
        if (i < NTASK) {
            int t = i / NN;
            int n = i - t * NN;
            const float* xw = s_x + t * NN * XS;

            // ---- sparse aggregation of x (f32x2) ----
            u64 y0 = 0, y1 = 0, y2 = 0, y3 = 0;
            const int cnt = s_cnt[n];
            const float* vrow = s_vals + n * NN;
            const unsigned char* crow = s_cols + n * NN;
            #pragma unroll 2
            for (int k = 0; k < cnt; k++) {
                u64 a2 = dup2(vrow[k]);
                int m = crow[k];
                const ulonglong2* xm = (const ulonglong2*)(xw + m * XS);
                ulonglong2 q0 = xm[0], q1 = xm[1];
                ffma2(y0, a2, q0.x); ffma2(y1, a2, q0.y);
                ffma2(y2, a2, q1.x); ffma2(y3, a2, q1.y);
            }

            // ---- FC1: h[32] = y[8] @ W1, f-outer, j-pairs packed ----
            float ys[8];
            unpack2(y0, ys[0], ys[1]); unpack2(y1, ys[2], ys[3]);
            unpack2(y2, ys[4], ys[5]); unpack2(y3, ys[6], ys[7]);
            u64 h[16];
            #pragma unroll
            for (int q = 0; q < 16; q++) h[q] = 0ull;
            #pragma unroll
            for (int f = 0; f < FIN; f++) {
                u64 yd = dup2(ys[f]);
                const ulonglong2* wr = (const ulonglong2*)(s_W1 + f * H1);
                #pragma unroll
                for (int q = 0; q < 8; q++) {
                    ulonglong2 w = wr[q];
                    ffma2(h[2 * q],     yd, w.x);
                    ffma2(h[2 * q + 1], yd, w.y);
                }
            }
            // relu (per-half)
            #pragma unroll
            for (int q = 0; q < 16; q++) {
                float a, bb2; unpack2(h[q], a, bb2);
                h[q] = pack2(fmaxf(a, 0.0f), fmaxf(bb2, 0.0f));
            }

            // ---- FC2: p[16] = h @ W2, c-outer, j-pairs packed ----
            float p[H2];
            #pragma unroll
            for (int c = 0; c < H2; c++) {
                u64 acc = 0ull;
                const ulonglong2* w2r = (const ulonglong2*)(s_W2t + c * 16);
                #pragma unroll
                for (int q = 0; q < 8; q++) {
                    ulonglong2 w = w2r[q];
                    ffma2(acc, h[2 * q],     w.x);
                    ffma2(acc, h[2 * q + 1], w.y);
                }
                float a, bb2; unpack2(acc, a, bb2);
                p[c] = a + bb2;
            }

            float* pr = s_p + (t * NN + n) * PS;
            *(float4*)(pr)      = make_float4(p[0],  p[1],  p[2],  p[3]);
            *(float4*)(pr + 4)  = make_float4(p[4],  p[5],  p[6],  p[7]);
            *(float4*)(pr + 8)  = make_float4(p[8],  p[9],  p[10], p[11]);
            *(float4*)(pr + 12) = make_float4(p[12], p[13], p[14], p[15]);
        }
    }
    __syncthreads();

    // =========== Phase B: per (t,n): sparse agg2 + sigmoid + store =========
    #pragma unroll 1
    for (int r = 0; r < 3; r++) {
        int i = tid + (r << 8);
        if (i < NTASK) {
            int t = i / NN;
            int n = i - t * NN;
            const float* pw = s_p + t * NN * PS;

            u64 z[8];
            #pragma unroll
            for (int q = 0; q < 8; q++) z[q] = 0ull;

            const int cnt = s_cnt[n];
            const float* vrow = s_vals + n * NN;
            const unsigned char* crow = s_cols + n * NN;
            #pragma unroll 2
            for (int k = 0; k < cnt; k++) {
                u64 a2 = dup2(vrow[k]);
                int m = crow[k];
                const ulonglong2* pm = (const ulonglong2*)(pw + m * PS);
                ulonglong2 q0 = pm[0], q1 = pm[1], q2 = pm[2], q3 = pm[3];
                ffma2(z[0], a2, q0.x); ffma2(z[1], a2, q0.y);
                ffma2(z[2], a2, q1.x); ffma2(z[3], a2, q1.y);
                ffma2(z[4], a2, q2.x); ffma2(z[5], a2, q2.y);
                ffma2(z[6], a2, q3.x); ffma2(z[7], a2, q3.y);
            }

            float o[H2];
            #pragma unroll
            for (int q = 0; q < 8; q++) {
                float a, bb2; unpack2(z[q], a, bb2);
                o[2 * q]     = 1.0f / (1.0f + __expf(-a));
                o[2 * q + 1] = 1.0f / (1.0f + __expf(-bb2));
            }

            float4* op = (float4*)(out + (((size_t)b * TT + t0 + t) * NN + n) * H2);
            op[0] = make_float4(o[0],  o[1],  o[2],  o[3]);
            op[1] = make_float4(o[4],  o[5],  o[6],  o[7]);
            op[2] = make_float4(o[8],  o[9],  o[10], o[11]);
            op[3] = make_float4(o[12], o[13], o[14], o[15]);
        }
    }
}

// ---------------------------------------------------------------------------
extern "C" void kernel_launch(void* const* d_in, const int* in_sizes, int n_in,
                              void* d_out, int out_size) {
    const float* x   = (const float*)d_in[0];   // [69, 32, 1024, 8]
    const float* adj = (const float*)d_in[1];   // [69, 69]
    const float* W1  = (const float*)d_in[2];   // [8, 32]
    const float* W2  = (const float*)d_in[3];   // [32, 16]
    float* out = (float*)d_out;                 // [32, 1024, 69, 16]

    prep_kernel<<<1, 256>>>(adj, W2);

    const int smem_bytes =
        (256 + 512 + TW * NN * XS + TW * NN * PS + NN * NN + NN) * 4
        + (NN * NN + 3);
    cudaFuncSetAttribute(gcn_kernel,
                         cudaFuncAttributeMaxDynamicSharedMemorySize, smem_bytes);
    gcn_kernel<<<(BB * TT) / TW, 256, smem_bytes>>>(x, W1, out);
}